// round 13
// baseline (speedup 1.0000x reference)
#include <cuda_runtime.h>

#define NPIX (512 * 512)
#define RB 6
#define RS 3
#define MAXVB (RB * NPIX + 2)
#define MAXVS (RS * NPIX + 2)
#define ALPHA_B 0.9696969696969697f   // 1/(1+2^-5)
#define ALPHA_S 0.8f                  // 1/(1+2^-2)
#define TPB 256                       // pixel kernels
#define BTPB 64                       // blur block size (finest wave granularity)
#define BITEMS 2
#define BCHUNK (BTPB * BITEMS)

// ---- static device scratch (no runtime allocation) ----
__device__ float4 g_SB[MAXVB];        // bilateral splat buffer
__device__ float4 g_PB[2][MAXVB];     // bilateral blur ping-pong
__device__ float4 g_SS[MAXVS];        // spatial splat buffer
__device__ float4 g_PS[2][MAXVS];     // spatial blur ping-pong
__device__ float  g_nB[2][MAXVB];     // scalar normalizer tables (bilateral)
__device__ float  g_nS[2][MAXVS];     // scalar normalizer tables (spatial)
__device__ float  g_coefB[NPIX];
__device__ float  g_coefS[NPIX];
// transposed index/weight arrays: [r][N] for coalesced per-r loads
__device__ int    g_osBT[RB * NPIX];
__device__ float  g_wsBT[RB * NPIX];
__device__ int    g_osST[RS * NPIX];
__device__ float  g_wsST[RS * NPIX];

__device__ __forceinline__ void red_v4(float4* p, float4 v) {
    asm volatile("red.global.add.v4.f32 [%0], {%1,%2,%3,%4};"
                 :: "l"(p), "f"(v.x), "f"(v.y), "f"(v.z), "f"(v.w) : "memory");
}

// ---------------------------------------------------------------------------
// One-time: transpose os/ws to [r][N] layout; zero normalizer + splat buffers.
__global__ void k_pre(const int* __restrict__ osB, const float* __restrict__ wsB,
                      const int* __restrict__ osS, const float* __restrict__ wsS,
                      int Mb, int Ms) {
    const int gsz = gridDim.x * blockDim.x;
    const int g0  = blockIdx.x * blockDim.x + threadIdx.x;
    for (int n = g0; n < NPIX; n += gsz) {
#pragma unroll
        for (int r = 0; r < RB; r++) {
            g_osBT[r * NPIX + n] = osB[n * RB + r];
            g_wsBT[r * NPIX + n] = wsB[n * RB + r];
        }
#pragma unroll
        for (int r = 0; r < RS; r++) {
            g_osST[r * NPIX + n] = osS[n * RS + r];
            g_wsST[r * NPIX + n] = wsS[n * RS + r];
        }
    }
    const float4 z4 = make_float4(0.f, 0.f, 0.f, 0.f);
    for (int i = g0; i < Mb + 1; i += gsz) { g_nB[0][i] = 0.f; g_SB[i] = z4; }
    for (int i = g0; i < Ms + 1; i += gsz) { g_nS[0][i] = 0.f; g_SS[i] = z4; }
}

// ---------------------------------------------------------------------------
// One-time: splat ones into scalar normalizer tables AND Q0=softmax(-u) into
// the float4 splat buffers.
__global__ void k_splat0(const float4* __restrict__ u4) {
    int n = blockIdx.x * TPB + threadIdx.x;
    if (n >= NPIX) return;

    float4 u = u4[n];
    float x0 = -u.x, x1 = -u.y, x2 = -u.z, x3 = -u.w;
    float m = fmaxf(fmaxf(x0, x1), fmaxf(x2, x3));
    float e0 = __expf(x0 - m), e1 = __expf(x1 - m);
    float e2 = __expf(x2 - m), e3 = __expf(x3 - m);
    float inv = 1.0f / (e0 + e1 + e2 + e3);
    float4 q = make_float4(e0 * inv, e1 * inv, e2 * inv, e3 * inv);

#pragma unroll
    for (int r = 0; r < RB; r++) {
        int   o = g_osBT[r * NPIX + n];
        float w = g_wsBT[r * NPIX + n];
        atomicAdd(&g_nB[0][o], w);
        red_v4(g_SB + o, make_float4(q.x * w, q.y * w, q.z * w, q.w * w));
    }
#pragma unroll
    for (int r = 0; r < RS; r++) {
        int   o = g_osST[r * NPIX + n];
        float w = g_wsST[r * NPIX + n];
        atomicAdd(&g_nS[0][o], w);
        red_v4(g_SS + o, make_float4(q.x * w, q.y * w, q.z * w, q.w * w));
    }
}

// ---------------------------------------------------------------------------
__device__ __forceinline__ void blur4_seg(const float4* __restrict__ in,
                                          float4* __restrict__ out,
                                          const int2* __restrict__ bn,
                                          int M, int blk) {
    const float4 z4 = make_float4(0.f, 0.f, 0.f, 0.f);
    int base = blk * BCHUNK + threadIdx.x;
    int2 nb[BITEMS];
#pragma unroll
    for (int k = 0; k < BITEMS; k++) {
        int i = base + k * BTPB;
        nb[k] = (i < M) ? bn[i] : make_int2(0, 0);
    }
    float4 a[BITEMS], b[BITEMS], c[BITEMS];
#pragma unroll
    for (int k = 0; k < BITEMS; k++) {
        int i = base + k * BTPB;
        a[k] = (i < M) ? in[i + 1] : z4;
        b[k] = in[nb[k].x];
        c[k] = in[nb[k].y];
    }
#pragma unroll
    for (int k = 0; k < BITEMS; k++) {
        int i = base + k * BTPB;
        if (i < M)
            out[i + 1] = make_float4(a[k].x + 0.5f * (b[k].x + c[k].x),
                                     a[k].y + 0.5f * (b[k].y + c[k].y),
                                     a[k].z + 0.5f * (b[k].z + c[k].z),
                                     a[k].w + 0.5f * (b[k].w + c[k].w));
    }
    if (blk == 0 && threadIdx.x == 0) out[0] = z4;
}

__device__ __forceinline__ void blur1_seg(const float* __restrict__ in,
                                          float* __restrict__ out,
                                          const int2* __restrict__ bn,
                                          int M, int blk) {
    int base = blk * BCHUNK + threadIdx.x;
    int2 nb[BITEMS];
#pragma unroll
    for (int k = 0; k < BITEMS; k++) {
        int i = base + k * BTPB;
        nb[k] = (i < M) ? bn[i] : make_int2(0, 0);
    }
    float a[BITEMS], b[BITEMS], c[BITEMS];
#pragma unroll
    for (int k = 0; k < BITEMS; k++) {
        int i = base + k * BTPB;
        a[k] = (i < M) ? in[i + 1] : 0.f;
        b[k] = in[nb[k].x];
        c[k] = in[nb[k].y];
    }
#pragma unroll
    for (int k = 0; k < BITEMS; k++) {
        int i = base + k * BTPB;
        if (i < M) out[i + 1] = a[k] + 0.5f * (b[k] + c[k]);
    }
    if (blk == 0 && threadIdx.x == 0) out[0] = 0.f;
}

// Segmented blur launch: [bilat f4][spat f4][bilat scalar][spat scalar][zero].
__global__ __launch_bounds__(BTPB)
void k_blur(const float4* __restrict__ ibf, float4* __restrict__ obf,
            const float4* __restrict__ isf, float4* __restrict__ osf,
            const float* __restrict__ ibs, float* __restrict__ obs,
            const float* __restrict__ iss, float* __restrict__ oss,
            const int2* __restrict__ bnB, const int2* __restrict__ bnS,
            int Mb, int Ms,
            int gB4, int gS4, int gB1, int gS1, int gZ,
            int zMb, int zMs) {
    int blk = blockIdx.x;
    if (blk < gB4) { blur4_seg(ibf, obf, bnB, Mb, blk); return; }
    blk -= gB4;
    if (blk < gS4) { blur4_seg(isf, osf, bnS, Ms, blk); return; }
    blk -= gS4;
    if (blk < gB1) { blur1_seg(ibs, obs, bnB, Mb, blk); return; }
    blk -= gB1;
    if (blk < gS1) { blur1_seg(iss, oss, bnS, Ms, blk); return; }
    blk -= gS1;
    // zero segment: clear splat buffers for the upcoming fused splat
    const float4 z4 = make_float4(0.f, 0.f, 0.f, 0.f);
    int stride = gZ * BTPB;
    for (int i = blk * BTPB + threadIdx.x; i < zMb; i += stride) g_SB[i] = z4;
    for (int i = blk * BTPB + threadIdx.x; i < zMs; i += stride) g_SS[i] = z4;
}

// ---------------------------------------------------------------------------
// Per-iteration: slice + message + softmax, then splat | final write.
// flags bit0: compute+store coef (first iteration); bit1: write output (last).
__global__ void k_fused(const float4* __restrict__ u4,
                        const float4* __restrict__ tB, const float4* __restrict__ tS,
                        float4* __restrict__ outQ, int flags) {
    int n = blockIdx.x * TPB + threadIdx.x;
    if (n >= NPIX) return;
    const float4 z4 = make_float4(0.f, 0.f, 0.f, 0.f);

    float cb, cs;
    if (flags & 1) {
        float sB = 0.f;
#pragma unroll
        for (int r = 0; r < RB; r++)
            sB = fmaf(g_nB[0][g_osBT[r * NPIX + n]], g_wsBT[r * NPIX + n], sB);
        cb = 10.0f * ALPHA_B / (ALPHA_B * sB + 1e-20f);
        g_coefB[n] = cb;
        float sS = 0.f;
#pragma unroll
        for (int r = 0; r < RS; r++)
            sS = fmaf(g_nS[1][g_osST[r * NPIX + n]], g_wsST[r * NPIX + n], sS);
        cs = 3.0f * ALPHA_S / (ALPHA_S * sS + 1e-20f);
        g_coefS[n] = cs;
    } else {
        cb = g_coefB[n];
        cs = g_coefS[n];
    }

    int   oB[RB]; float wB[RB];
#pragma unroll
    for (int r = 0; r < RB; r++) {
        oB[r] = g_osBT[r * NPIX + n];
        wB[r] = g_wsBT[r * NPIX + n];
    }
    int   oS[RS]; float wS[RS];
#pragma unroll
    for (int r = 0; r < RS; r++) {
        oS[r] = g_osST[r * NPIX + n];
        wS[r] = g_wsST[r * NPIX + n];
    }

    float4 fb = z4;
#pragma unroll
    for (int r = 0; r < RB; r++) {
        float4 t = tB[oB[r]];
        fb.x = fmaf(t.x, wB[r], fb.x); fb.y = fmaf(t.y, wB[r], fb.y);
        fb.z = fmaf(t.z, wB[r], fb.z); fb.w = fmaf(t.w, wB[r], fb.w);
    }
    float4 fs = z4;
#pragma unroll
    for (int r = 0; r < RS; r++) {
        float4 t = tS[oS[r]];
        fs.x = fmaf(t.x, wS[r], fs.x); fs.y = fmaf(t.y, wS[r], fs.y);
        fs.z = fmaf(t.z, wS[r], fs.z); fs.w = fmaf(t.w, wS[r], fs.w);
    }

    float4 u = u4[n];
    float x0 = fmaf(fb.x, cb, fmaf(fs.x, cs, -u.x));
    float x1 = fmaf(fb.y, cb, fmaf(fs.y, cs, -u.y));
    float x2 = fmaf(fb.z, cb, fmaf(fs.z, cs, -u.z));
    float x3 = fmaf(fb.w, cb, fmaf(fs.w, cs, -u.w));

    float m = fmaxf(fmaxf(x0, x1), fmaxf(x2, x3));
    float e0 = __expf(x0 - m), e1 = __expf(x1 - m);
    float e2 = __expf(x2 - m), e3 = __expf(x3 - m);
    float inv = 1.0f / (e0 + e1 + e2 + e3);
    float4 q = make_float4(e0 * inv, e1 * inv, e2 * inv, e3 * inv);

    if (flags & 2) {
        outQ[n] = q;
        return;
    }
#pragma unroll
    for (int r = 0; r < RB; r++)
        red_v4(g_SB + oB[r], make_float4(q.x * wB[r], q.y * wB[r], q.z * wB[r], q.w * wB[r]));
#pragma unroll
    for (int r = 0; r < RS; r++)
        red_v4(g_SS + oS[r], make_float4(q.x * wS[r], q.y * wS[r], q.z * wS[r], q.w * wS[r]));
}

// ---------------------------------------------------------------------------
extern "C" void kernel_launch(void* const* d_in, const int* in_sizes, int n_in,
                              void* d_out, int out_size) {
    const float4* u4  = (const float4*)d_in[0];
    const float*  wsB = (const float*)d_in[1];
    const int*    osB = (const int*)d_in[2];
    const int*    bnB = (const int*)d_in[3];
    const float*  wsS = (const float*)d_in[5];
    const int*    osS = (const int*)d_in[6];
    const int*    bnS = (const int*)d_in[7];

    const int Mb = in_sizes[3] / (2 * RB);
    const int Ms = in_sizes[7] / (2 * RS);

    float4 *SB, *PB, *SS, *PS;
    float *nB, *nS;
    cudaGetSymbolAddress((void**)&SB, g_SB);
    cudaGetSymbolAddress((void**)&PB, g_PB);
    cudaGetSymbolAddress((void**)&SS, g_SS);
    cudaGetSymbolAddress((void**)&PS, g_PS);
    cudaGetSymbolAddress((void**)&nB, g_nB);
    cudaGetSymbolAddress((void**)&nS, g_nS);
    float4* PBb[2] = { PB, PB + MAXVB };
    float4* PSb[2] = { PS, PS + MAXVS };
    float*  nBb[2] = { nB, nB + MAXVB };
    float*  nSb[2] = { nS, nS + MAXVS };

    const int GN    = (NPIX + TPB - 1) / TPB;
    const int gB    = (Mb + BCHUNK - 1) / BCHUNK;
    const int gS    = (Ms + BCHUNK - 1) / BCHUNK;
    const int nBlkZ = 512;

    // one-time: transpose + zero
    k_pre<<<1184, TPB>>>(osB, wsB, osS, wsS, Mb, Ms);
    // one-time: splat ones (scalar) + Q0 (float4)
    k_splat0<<<GN, TPB>>>(u4);

    for (int it = 0; it < 10; it++) {
        const int scalarOn = (it == 0);
        for (int j = 0; j < RB; j++) {
            const int sAct = (j < RS);
            const int gB4 = gB;
            const int gS4 = sAct ? gS : 0;
            const int gB1 = scalarOn ? gB : 0;
            const int gS1 = (scalarOn && sAct) ? gS : 0;
            const int gZ  = (j == 1) ? nBlkZ : 0;

            const float4* ibf = (j == 0) ? SB : PBb[1 - (j & 1)];
            float4*       obf = PBb[j & 1];
            const float4* isf = (j == 0) ? SS : PSb[1 - (j & 1)];
            float4*       osf = PSb[j & 1];
            const float*  ibs = nBb[j & 1];
            float*        obs = nBb[(j + 1) & 1];
            const float*  iss = nSb[j & 1];
            float*        oss = nSb[(j + 1) & 1];

            k_blur<<<gB4 + gS4 + gB1 + gS1 + gZ, BTPB>>>(
                ibf, obf, sAct ? isf : nullptr, sAct ? osf : nullptr,
                ibs, obs, iss, oss,
                (const int2*)(bnB + (size_t)j * 2 * Mb),
                sAct ? (const int2*)(bnS + (size_t)j * 2 * Ms) : nullptr,
                Mb, Ms, gB4, gS4, gB1, gS1, gZ,
                (j == 1) ? Mb + 1 : 0, (j == 1) ? Ms + 1 : 0);
        }
        // bilateral final PBb[1] (6 passes), spatial final PSb[0] (3 passes)
        int flags = (it == 0 ? 1 : 0) | (it == 9 ? 2 : 0);
        k_fused<<<GN, TPB>>>(u4, PBb[1], PSb[0], (float4*)d_out, flags);
    }
}

// round 14
// speedup vs baseline: 1.0204x; 1.0204x over previous
#include <cuda_runtime.h>

#define NPIX (512 * 512)
#define RB 6
#define RS 3
#define MAXVB (RB * NPIX + 2)
#define MAXVS (RS * NPIX + 2)
#define ALPHA_B 0.9696969696969697f   // 1/(1+2^-5)
#define ALPHA_S 0.8f                  // 1/(1+2^-2)
#define TPB 256                       // init kernels
#define FTPB 128                      // fused kernel block size (fine tail)
#define BTPB 128                      // blur block size (empirical optimum)
#define BITEMS 2
#define BCHUNK (BTPB * BITEMS)

// ---- static device scratch (no runtime allocation) ----
__device__ float4 g_SB[MAXVB];        // bilateral splat buffer
__device__ float4 g_PB[2][MAXVB];     // bilateral blur ping-pong
__device__ float4 g_SS[MAXVS];        // spatial splat buffer
__device__ float4 g_PS[2][MAXVS];     // spatial blur ping-pong
__device__ float  g_nB[2][MAXVB];     // scalar normalizer tables (bilateral)
__device__ float  g_nS[2][MAXVS];     // scalar normalizer tables (spatial)
__device__ float  g_coefB[NPIX];
__device__ float  g_coefS[NPIX];
// transposed index/weight arrays: [r][N] for coalesced per-r loads
__device__ int    g_osBT[RB * NPIX];
__device__ float  g_wsBT[RB * NPIX];
__device__ int    g_osST[RS * NPIX];
__device__ float  g_wsST[RS * NPIX];

__device__ __forceinline__ void red_v4(float4* p, float4 v) {
    asm volatile("red.global.add.v4.f32 [%0], {%1,%2,%3,%4};"
                 :: "l"(p), "f"(v.x), "f"(v.y), "f"(v.z), "f"(v.w) : "memory");
}

// ---------------------------------------------------------------------------
// One-time: transpose os/ws to [r][N] layout; zero normalizer + splat buffers.
__global__ void k_pre(const int* __restrict__ osB, const float* __restrict__ wsB,
                      const int* __restrict__ osS, const float* __restrict__ wsS,
                      int Mb, int Ms) {
    const int gsz = gridDim.x * blockDim.x;
    const int g0  = blockIdx.x * blockDim.x + threadIdx.x;
    for (int n = g0; n < NPIX; n += gsz) {
#pragma unroll
        for (int r = 0; r < RB; r++) {
            g_osBT[r * NPIX + n] = osB[n * RB + r];
            g_wsBT[r * NPIX + n] = wsB[n * RB + r];
        }
#pragma unroll
        for (int r = 0; r < RS; r++) {
            g_osST[r * NPIX + n] = osS[n * RS + r];
            g_wsST[r * NPIX + n] = wsS[n * RS + r];
        }
    }
    const float4 z4 = make_float4(0.f, 0.f, 0.f, 0.f);
    for (int i = g0; i < Mb + 1; i += gsz) { g_nB[0][i] = 0.f; g_SB[i] = z4; }
    for (int i = g0; i < Ms + 1; i += gsz) { g_nS[0][i] = 0.f; g_SS[i] = z4; }
}

// ---------------------------------------------------------------------------
// One-time: splat ones into scalar normalizer tables AND Q0=softmax(-u) into
// the float4 splat buffers.
__global__ void k_splat0(const float4* __restrict__ u4) {
    int n = blockIdx.x * TPB + threadIdx.x;
    if (n >= NPIX) return;

    float4 u = u4[n];
    float x0 = -u.x, x1 = -u.y, x2 = -u.z, x3 = -u.w;
    float m = fmaxf(fmaxf(x0, x1), fmaxf(x2, x3));
    float e0 = __expf(x0 - m), e1 = __expf(x1 - m);
    float e2 = __expf(x2 - m), e3 = __expf(x3 - m);
    float inv = 1.0f / (e0 + e1 + e2 + e3);
    float4 q = make_float4(e0 * inv, e1 * inv, e2 * inv, e3 * inv);

#pragma unroll
    for (int r = 0; r < RB; r++) {
        int   o = g_osBT[r * NPIX + n];
        float w = g_wsBT[r * NPIX + n];
        atomicAdd(&g_nB[0][o], w);
        red_v4(g_SB + o, make_float4(q.x * w, q.y * w, q.z * w, q.w * w));
    }
#pragma unroll
    for (int r = 0; r < RS; r++) {
        int   o = g_osST[r * NPIX + n];
        float w = g_wsST[r * NPIX + n];
        atomicAdd(&g_nS[0][o], w);
        red_v4(g_SS + o, make_float4(q.x * w, q.y * w, q.z * w, q.w * w));
    }
}

// ---------------------------------------------------------------------------
__device__ __forceinline__ void blur4_seg(const float4* __restrict__ in,
                                          float4* __restrict__ out,
                                          const int2* __restrict__ bn,
                                          int M, int blk) {
    const float4 z4 = make_float4(0.f, 0.f, 0.f, 0.f);
    int base = blk * BCHUNK + threadIdx.x;
    int2 nb[BITEMS];
#pragma unroll
    for (int k = 0; k < BITEMS; k++) {
        int i = base + k * BTPB;
        nb[k] = (i < M) ? bn[i] : make_int2(0, 0);
    }
    float4 a[BITEMS], b[BITEMS], c[BITEMS];
#pragma unroll
    for (int k = 0; k < BITEMS; k++) {
        int i = base + k * BTPB;
        a[k] = (i < M) ? in[i + 1] : z4;
        b[k] = in[nb[k].x];
        c[k] = in[nb[k].y];
    }
#pragma unroll
    for (int k = 0; k < BITEMS; k++) {
        int i = base + k * BTPB;
        if (i < M)
            out[i + 1] = make_float4(a[k].x + 0.5f * (b[k].x + c[k].x),
                                     a[k].y + 0.5f * (b[k].y + c[k].y),
                                     a[k].z + 0.5f * (b[k].z + c[k].z),
                                     a[k].w + 0.5f * (b[k].w + c[k].w));
    }
    if (blk == 0 && threadIdx.x == 0) out[0] = z4;
}

__device__ __forceinline__ void blur1_seg(const float* __restrict__ in,
                                          float* __restrict__ out,
                                          const int2* __restrict__ bn,
                                          int M, int blk) {
    int base = blk * BCHUNK + threadIdx.x;
    int2 nb[BITEMS];
#pragma unroll
    for (int k = 0; k < BITEMS; k++) {
        int i = base + k * BTPB;
        nb[k] = (i < M) ? bn[i] : make_int2(0, 0);
    }
    float a[BITEMS], b[BITEMS], c[BITEMS];
#pragma unroll
    for (int k = 0; k < BITEMS; k++) {
        int i = base + k * BTPB;
        a[k] = (i < M) ? in[i + 1] : 0.f;
        b[k] = in[nb[k].x];
        c[k] = in[nb[k].y];
    }
#pragma unroll
    for (int k = 0; k < BITEMS; k++) {
        int i = base + k * BTPB;
        if (i < M) out[i + 1] = a[k] + 0.5f * (b[k] + c[k]);
    }
    if (blk == 0 && threadIdx.x == 0) out[0] = 0.f;
}

// Segmented blur launch: [bilat f4][spat f4][bilat scalar][spat scalar][zero].
__global__ __launch_bounds__(BTPB)
void k_blur(const float4* __restrict__ ibf, float4* __restrict__ obf,
            const float4* __restrict__ isf, float4* __restrict__ osf,
            const float* __restrict__ ibs, float* __restrict__ obs,
            const float* __restrict__ iss, float* __restrict__ oss,
            const int2* __restrict__ bnB, const int2* __restrict__ bnS,
            int Mb, int Ms,
            int gB4, int gS4, int gB1, int gS1, int gZ,
            int zMb, int zMs) {
    int blk = blockIdx.x;
    if (blk < gB4) { blur4_seg(ibf, obf, bnB, Mb, blk); return; }
    blk -= gB4;
    if (blk < gS4) { blur4_seg(isf, osf, bnS, Ms, blk); return; }
    blk -= gS4;
    if (blk < gB1) { blur1_seg(ibs, obs, bnB, Mb, blk); return; }
    blk -= gB1;
    if (blk < gS1) { blur1_seg(iss, oss, bnS, Ms, blk); return; }
    blk -= gS1;
    // zero segment: clear splat buffers for the upcoming fused splat
    const float4 z4 = make_float4(0.f, 0.f, 0.f, 0.f);
    int stride = gZ * BTPB;
    for (int i = blk * BTPB + threadIdx.x; i < zMb; i += stride) g_SB[i] = z4;
    for (int i = blk * BTPB + threadIdx.x; i < zMs; i += stride) g_SS[i] = z4;
}

// ---------------------------------------------------------------------------
// Per-iteration: slice + message + softmax, then splat | final write.
// flags bit0: compute+store coef (first iteration); bit1: write output (last).
__global__ __launch_bounds__(FTPB)
void k_fused(const float4* __restrict__ u4,
             const float4* __restrict__ tB, const float4* __restrict__ tS,
             float4* __restrict__ outQ, int flags) {
    int n = blockIdx.x * FTPB + threadIdx.x;
    if (n >= NPIX) return;
    const float4 z4 = make_float4(0.f, 0.f, 0.f, 0.f);

    float cb, cs;
    if (flags & 1) {
        float sB = 0.f;
#pragma unroll
        for (int r = 0; r < RB; r++)
            sB = fmaf(g_nB[0][g_osBT[r * NPIX + n]], g_wsBT[r * NPIX + n], sB);
        cb = 10.0f * ALPHA_B / (ALPHA_B * sB + 1e-20f);
        g_coefB[n] = cb;
        float sS = 0.f;
#pragma unroll
        for (int r = 0; r < RS; r++)
            sS = fmaf(g_nS[1][g_osST[r * NPIX + n]], g_wsST[r * NPIX + n], sS);
        cs = 3.0f * ALPHA_S / (ALPHA_S * sS + 1e-20f);
        g_coefS[n] = cs;
    } else {
        cb = g_coefB[n];
        cs = g_coefS[n];
    }

    int   oB[RB]; float wB[RB];
#pragma unroll
    for (int r = 0; r < RB; r++) {
        oB[r] = g_osBT[r * NPIX + n];
        wB[r] = g_wsBT[r * NPIX + n];
    }
    int   oS[RS]; float wS[RS];
#pragma unroll
    for (int r = 0; r < RS; r++) {
        oS[r] = g_osST[r * NPIX + n];
        wS[r] = g_wsST[r * NPIX + n];
    }

    float4 fb = z4;
#pragma unroll
    for (int r = 0; r < RB; r++) {
        float4 t = tB[oB[r]];
        fb.x = fmaf(t.x, wB[r], fb.x); fb.y = fmaf(t.y, wB[r], fb.y);
        fb.z = fmaf(t.z, wB[r], fb.z); fb.w = fmaf(t.w, wB[r], fb.w);
    }
    float4 fs = z4;
#pragma unroll
    for (int r = 0; r < RS; r++) {
        float4 t = tS[oS[r]];
        fs.x = fmaf(t.x, wS[r], fs.x); fs.y = fmaf(t.y, wS[r], fs.y);
        fs.z = fmaf(t.z, wS[r], fs.z); fs.w = fmaf(t.w, wS[r], fs.w);
    }

    float4 u = u4[n];
    float x0 = fmaf(fb.x, cb, fmaf(fs.x, cs, -u.x));
    float x1 = fmaf(fb.y, cb, fmaf(fs.y, cs, -u.y));
    float x2 = fmaf(fb.z, cb, fmaf(fs.z, cs, -u.z));
    float x3 = fmaf(fb.w, cb, fmaf(fs.w, cs, -u.w));

    float m = fmaxf(fmaxf(x0, x1), fmaxf(x2, x3));
    float e0 = __expf(x0 - m), e1 = __expf(x1 - m);
    float e2 = __expf(x2 - m), e3 = __expf(x3 - m);
    float inv = 1.0f / (e0 + e1 + e2 + e3);
    float4 q = make_float4(e0 * inv, e1 * inv, e2 * inv, e3 * inv);

    if (flags & 2) {
        outQ[n] = q;
        return;
    }
#pragma unroll
    for (int r = 0; r < RB; r++)
        red_v4(g_SB + oB[r], make_float4(q.x * wB[r], q.y * wB[r], q.z * wB[r], q.w * wB[r]));
#pragma unroll
    for (int r = 0; r < RS; r++)
        red_v4(g_SS + oS[r], make_float4(q.x * wS[r], q.y * wS[r], q.z * wS[r], q.w * wS[r]));
}

// ---------------------------------------------------------------------------
extern "C" void kernel_launch(void* const* d_in, const int* in_sizes, int n_in,
                              void* d_out, int out_size) {
    const float4* u4  = (const float4*)d_in[0];
    const float*  wsB = (const float*)d_in[1];
    const int*    osB = (const int*)d_in[2];
    const int*    bnB = (const int*)d_in[3];
    const float*  wsS = (const float*)d_in[5];
    const int*    osS = (const int*)d_in[6];
    const int*    bnS = (const int*)d_in[7];

    const int Mb = in_sizes[3] / (2 * RB);
    const int Ms = in_sizes[7] / (2 * RS);

    float4 *SB, *PB, *SS, *PS;
    float *nB, *nS;
    cudaGetSymbolAddress((void**)&SB, g_SB);
    cudaGetSymbolAddress((void**)&PB, g_PB);
    cudaGetSymbolAddress((void**)&SS, g_SS);
    cudaGetSymbolAddress((void**)&PS, g_PS);
    cudaGetSymbolAddress((void**)&nB, g_nB);
    cudaGetSymbolAddress((void**)&nS, g_nS);
    float4* PBb[2] = { PB, PB + MAXVB };
    float4* PSb[2] = { PS, PS + MAXVS };
    float*  nBb[2] = { nB, nB + MAXVB };
    float*  nSb[2] = { nS, nS + MAXVS };

    const int GN    = (NPIX + TPB - 1) / TPB;
    const int GF    = (NPIX + FTPB - 1) / FTPB;
    const int gB    = (Mb + BCHUNK - 1) / BCHUNK;
    const int gS    = (Ms + BCHUNK - 1) / BCHUNK;
    const int nBlkZ = 256;

    // one-time: transpose + zero
    k_pre<<<1184, TPB>>>(osB, wsB, osS, wsS, Mb, Ms);
    // one-time: splat ones (scalar) + Q0 (float4)
    k_splat0<<<GN, TPB>>>(u4);

    for (int it = 0; it < 10; it++) {
        const int scalarOn = (it == 0);
        for (int j = 0; j < RB; j++) {
            const int sAct = (j < RS);
            const int gB4 = gB;
            const int gS4 = sAct ? gS : 0;
            const int gB1 = scalarOn ? gB : 0;
            const int gS1 = (scalarOn && sAct) ? gS : 0;
            const int gZ  = (j == 1) ? nBlkZ : 0;

            const float4* ibf = (j == 0) ? SB : PBb[1 - (j & 1)];
            float4*       obf = PBb[j & 1];
            const float4* isf = (j == 0) ? SS : PSb[1 - (j & 1)];
            float4*       osf = PSb[j & 1];
            const float*  ibs = nBb[j & 1];
            float*        obs = nBb[(j + 1) & 1];
            const float*  iss = nSb[j & 1];
            float*        oss = nSb[(j + 1) & 1];

            k_blur<<<gB4 + gS4 + gB1 + gS1 + gZ, BTPB>>>(
                ibf, obf, sAct ? isf : nullptr, sAct ? osf : nullptr,
                ibs, obs, iss, oss,
                (const int2*)(bnB + (size_t)j * 2 * Mb),
                sAct ? (const int2*)(bnS + (size_t)j * 2 * Ms) : nullptr,
                Mb, Ms, gB4, gS4, gB1, gS1, gZ,
                (j == 1) ? Mb + 1 : 0, (j == 1) ? Ms + 1 : 0);
        }
        // bilateral final PBb[1] (6 passes), spatial final PSb[0] (3 passes)
        int flags = (it == 0 ? 1 : 0) | (it == 9 ? 2 : 0);
        k_fused<<<GF, FTPB>>>(u4, PBb[1], PSb[0], (float4*)d_out, flags);
    }
}